// round 2
// baseline (speedup 1.0000x reference)
#include <cuda_runtime.h>

// Scalar damped-Newton minimization of a degree-6 polynomial.
// Inputs (metadata order): d_in[0] = poly (7 x float32, lowest-degree first),
//                          d_in[1] = x_init (1 x float32)
// Output: 1 x float32 = x_min.
//
// Replicates the JAX lax.while_loop:
//   cond: g2 > 1e-12 && it < 100
//   body: g = p'(x); h = p''(x); step = (h > 0) ? g/h : 0.1*g;
//         x -= step; g2 = p'(x)^2; it++
// initial g2 = inf, so at least one iteration runs.

#define MAX_ITER 100
#define GRAD_SQ_TOL 1e-12f

__global__ void polymin_kernel(const float* __restrict__ poly,
                               const float* __restrict__ x_init,
                               float* __restrict__ out) {
    // Load the 7 coefficients (lowest-degree first).
    float c0 = poly[0], c1 = poly[1], c2 = poly[2], c3 = poly[3];
    float c4 = poly[4], c5 = poly[5], c6 = poly[6];
    (void)c0;

    // p'(x): d1[k] = poly[k+1] * (k+1), degree 5 (6 coefficients)
    float d1_0 = c1 * 1.0f;
    float d1_1 = c2 * 2.0f;
    float d1_2 = c3 * 3.0f;
    float d1_3 = c4 * 4.0f;
    float d1_4 = c5 * 5.0f;
    float d1_5 = c6 * 6.0f;

    // p''(x): d2[k] = d1[k+1] * (k+1), degree 4 (5 coefficients)
    float d2_0 = d1_1 * 1.0f;
    float d2_1 = d1_2 * 2.0f;
    float d2_2 = d1_3 * 3.0f;
    float d2_3 = d1_4 * 4.0f;
    float d2_4 = d1_5 * 5.0f;

    float x = x_init[0];
    float g2 = __int_as_float(0x7f800000);  // +inf

    #pragma unroll 1
    for (int it = 0; it < MAX_ITER; ++it) {
        if (!(g2 > GRAD_SQ_TOL)) break;

        // g = p'(x) via Horner
        float g = d1_5;
        g = fmaf(g, x, d1_4);
        g = fmaf(g, x, d1_3);
        g = fmaf(g, x, d1_2);
        g = fmaf(g, x, d1_1);
        g = fmaf(g, x, d1_0);

        // h = p''(x) via Horner
        float h = d2_4;
        h = fmaf(h, x, d2_3);
        h = fmaf(h, x, d2_2);
        h = fmaf(h, x, d2_1);
        h = fmaf(h, x, d2_0);

        float step = (h > 0.0f) ? (g / h) : (0.1f * g);
        x = x - step;

        // g_new = p'(x_new)
        float gn = d1_5;
        gn = fmaf(gn, x, d1_4);
        gn = fmaf(gn, x, d1_3);
        gn = fmaf(gn, x, d1_2);
        gn = fmaf(gn, x, d1_1);
        gn = fmaf(gn, x, d1_0);

        g2 = gn * gn;
    }

    out[0] = x;
}

extern "C" void kernel_launch(void* const* d_in, const int* in_sizes, int n_in,
                              void* d_out, int out_size) {
    const float* poly   = (const float*)d_in[0];
    const float* x_init = (const float*)d_in[1];
    float* out = (float*)d_out;
    polymin_kernel<<<1, 1>>>(poly, x_init, out);
}